// round 10
// baseline (speedup 1.0000x reference)
#include <cuda_runtime.h>
#include <cuda_bf16.h>
#include <cstdint>

// out[n,i,j,k] = sum_{a,b,c} x[n,a,b,c] w0[a,i] w1[b,j] w2[c,k]
// Three in-smem stages of D[q,i] = sum_p A[q,p] w[p,i]  (M=1024, N=32, K=32).
// A row (128B, swzA): K=64 bf16 interleaved [hi(p0),lo(p0),hi(p1),lo(p1),...].
// Pass1 B row i: [w_hi(p),w_hi(p)] -> hi*w_hi + lo*w_hi.  Pass2: [w_lo(p),0] -> hi*w_lo.
// (lo*w_lo ~2^-18 dropped.) fp32 accumulation in mma.sync fragments.
// R9: D stays in registers; epilogue scatters bf16-split words DIRECTLY into the
// A buffer (st.shared.v2, pairing columns 2w/2w+1) -- no fp32 scratch, no gather,
// 5 barriers total instead of 13.

#define NT 512
#define ELEMS 32768
#define A_OFF 0u
#define B_OFF 131072u            // A: 1024 rows * 128B
#define SMEM_TOTAL 155648        // + B: 3 stages * 2 passes * 4KB

// A-buffer swizzle: banks get XOR of row bits[2:0] AND row bits[5:3]
// (bijective; consistent across prologue / MMA reads / epilogue scatter)
static __device__ __forceinline__ uint32_t swzA(uint32_t b) {
    return b ^ ((b >> 3) & 0x70u) ^ ((b >> 8) & 0x70u);
}
// B-buffer swizzle: standard SW128
static __device__ __forceinline__ uint32_t swzB(uint32_t b) { return b ^ ((b >> 3) & 0x70u); }

static __device__ __forceinline__ uint32_t smem_u32(const void* p) {
    uint32_t a;
    asm("{ .reg .u64 t; cvta.to.shared.u64 t, %1; cvt.u32.u64 %0, t; }" : "=r"(a) : "l"(p));
    return a;
}
static __device__ __forceinline__ void sts128(uint32_t a, uint32_t x, uint32_t y, uint32_t z, uint32_t w) {
    asm volatile("st.shared.v4.b32 [%0], {%1,%2,%3,%4};" :: "r"(a), "r"(x), "r"(y), "r"(z), "r"(w) : "memory");
}
static __device__ __forceinline__ void sts64(uint32_t a, uint32_t x, uint32_t y) {
    asm volatile("st.shared.v2.b32 [%0], {%1,%2};" :: "r"(a), "r"(x), "r"(y) : "memory");
}
static __device__ __forceinline__ void sts32(uint32_t a, uint32_t v) {
    asm volatile("st.shared.b32 [%0], %1;" :: "r"(a), "r"(v) : "memory");
}
static __device__ __forceinline__ uint32_t lds32(uint32_t a) {
    uint32_t v; asm volatile("ld.shared.b32 %0, [%1];" : "=r"(v) : "r"(a)); return v;
}

// (bf16(e1) << 16) | bf16(e0)
static __device__ __forceinline__ uint32_t cvt2(float e1, float e0) {
    uint32_t r;
    asm("cvt.rn.bf16x2.f32 %0, %1, %2;" : "=r"(r) : "f"(e1), "f"(e0));
    return r;
}
// one fp32 -> packed (lo_bf16 << 16) | hi_bf16  == A-row word [hi at even k, lo at odd k]
static __device__ __forceinline__ uint32_t splitw(float v) {
    uint32_t hp = cvt2(0.0f, v);
    float hf = __uint_as_float(hp << 16);
    return cvt2(v - hf, v);
}

static __device__ __forceinline__ void mma16816(float* c,
                                                uint32_t a0, uint32_t a1, uint32_t a2, uint32_t a3,
                                                uint32_t b0, uint32_t b1) {
    asm volatile(
        "mma.sync.aligned.m16n8k16.row.col.f32.bf16.bf16.f32 "
        "{%0,%1,%2,%3}, {%4,%5,%6,%7}, {%8,%9}, {%0,%1,%2,%3};"
        : "+f"(c[0]), "+f"(c[1]), "+f"(c[2]), "+f"(c[3])
        : "r"(a0), "r"(a1), "r"(a2), "r"(a3), "r"(b0), "r"(b1));
}

__global__ __launch_bounds__(NT, 1)
void kron3_mma_kernel(const float* __restrict__ x,
                      const float* __restrict__ w0,
                      const float* __restrict__ w1,
                      const float* __restrict__ w2,
                      float* __restrict__ out) {
    extern __shared__ __align__(16) char smem[];
    const uint32_t sb = smem_u32(smem);

    const int tid = threadIdx.x;
    const int w = tid >> 5;            // 0..15
    const int lane = tid & 31;
    const int lr = lane >> 2;          // fragment row within 8
    const int lc = lane & 3;           // fragment col group
    const long long nb = blockIdx.x;

    // ---- weight prep: per stage, pass1 rows [w_hi|w_hi], pass2 rows [w_lo|0] ----
    if (tid < 96) {
        const int s = tid >> 5;
        const int i = tid & 31;
        const float* ws = (s == 0) ? w0 : (s == 1) ? w1 : w2;
        const uint32_t b1 = sb + B_OFF + (uint32_t)s * 8192u;
        const uint32_t b2 = b1 + 4096u;
        #pragma unroll 4
        for (int p = 0; p < 32; ++p) {
            float v = ws[p * 32 + i];
            uint32_t hp = cvt2(0.0f, v);                 // bf16(v) in low half
            float hf = __uint_as_float(hp << 16);
            uint32_t w1w = cvt2(v, v);                   // [hi|hi]
            uint32_t w2w = cvt2(0.0f, v - hf);           // [lo|0]
            uint32_t ro = (uint32_t)(i * 128 + 4 * p);
            sts32(b1 + swzB(ro), w1w);
            sts32(b2 + swzB(ro), w2w);
        }
    }

    // ---- prologue: x (global, coalesced) -> interleaved split A rows ----
    {
        const float* xb = x + nb * ELEMS;
        #pragma unroll 1
        for (int rr = 0; rr < 2; ++rr) {
            const int q = tid + rr * NT;
            float v[32];
            #pragma unroll
            for (int p = 0; p < 32; ++p) v[p] = xb[p * 1024 + q];
            const uint32_t base = (uint32_t)q * 128u;
            #pragma unroll
            for (int j = 0; j < 8; ++j) {
                uint32_t w0w = splitw(v[4 * j + 0]);
                uint32_t w1w = splitw(v[4 * j + 1]);
                uint32_t w2w = splitw(v[4 * j + 2]);
                uint32_t w3w = splitw(v[4 * j + 3]);
                sts128(sb + A_OFF + swzA(base + 16u * j), w0w, w1w, w2w, w3w);
            }
        }
    }
    __syncthreads();

    // ---- 3 stages ----
    #pragma unroll 1
    for (int s = 0; s < 3; ++s) {
        const uint32_t b1 = sb + B_OFF + (uint32_t)s * 8192u;
        const uint32_t b2 = b1 + 4096u;

        float cc[4][4][4];
        #pragma unroll
        for (int mt = 0; mt < 4; ++mt)
            #pragma unroll
            for (int nt = 0; nt < 4; ++nt)
                #pragma unroll
                for (int e = 0; e < 4; ++e) cc[mt][nt][e] = 0.0f;

        #pragma unroll
        for (int kb = 0; kb < 4; ++kb) {
            const uint32_t kbyte = (uint32_t)(kb * 32 + lc * 4);
            // A fragments for all 4 m-tiles at this k-block (16 regs)
            uint32_t a[4][4];
            #pragma unroll
            for (int mt = 0; mt < 4; ++mt) {
                const uint32_t qlo = (uint32_t)(w * 64 + mt * 16 + lr);
                a[mt][0] = lds32(sb + A_OFF + swzA(qlo * 128u + kbyte));
                a[mt][1] = lds32(sb + A_OFF + swzA((qlo + 8u) * 128u + kbyte));
                a[mt][2] = lds32(sb + A_OFF + swzA(qlo * 128u + kbyte + 16u));
                a[mt][3] = lds32(sb + A_OFF + swzA((qlo + 8u) * 128u + kbyte + 16u));
            }
            #pragma unroll
            for (int nt = 0; nt < 4; ++nt) {
                const uint32_t byte = (uint32_t)((nt * 8 + lr) * 128) + kbyte;
                uint32_t b10 = lds32(b1 + swzB(byte));
                uint32_t b11 = lds32(b1 + swzB(byte + 16u));
                uint32_t b20 = lds32(b2 + swzB(byte));
                uint32_t b21 = lds32(b2 + swzB(byte + 16u));
                #pragma unroll
                for (int mt = 0; mt < 4; ++mt) {
                    mma16816(cc[mt][nt], a[mt][0], a[mt][1], a[mt][2], a[mt][3], b10, b11);
                    mma16816(cc[mt][nt], a[mt][0], a[mt][1], a[mt][2], a[mt][3], b20, b21);
                }
            }
        }

        if (s < 2) {
            // all A reads for this stage complete before overwriting
            __syncthreads();
            // direct scatter: D[q,i] -> A'[(q&31)*32+i][p2=q>>5], split in producer.
            // mt pair (mt2, mt2+2) gives columns p2 = 2w, 2w+1 -> one 8B vector store.
            #pragma unroll
            for (int mt2 = 0; mt2 < 2; ++mt2) {
                #pragma unroll
                for (int nt = 0; nt < 4; ++nt) {
                    #pragma unroll
                    for (int e = 0; e < 4; ++e) {
                        const uint32_t r2 = (uint32_t)((mt2 * 16 + lr + 8 * (e >> 1)) * 32
                                                       + nt * 8 + lc * 2 + (e & 1));
                        const uint32_t addr = sb + A_OFF + swzA(r2 * 128u + 8u * (uint32_t)w);
                        sts64(addr, splitw(cc[mt2][nt][e]), splitw(cc[mt2 + 2][nt][e]));
                    }
                }
            }
            __syncthreads();
        } else {
            // final: c regs -> global out (fp32), 8B stores filling exact 32B sectors
            float* ob = out + nb * ELEMS;
            #pragma unroll
            for (int mt = 0; mt < 4; ++mt) {
                const int q = w * 64 + mt * 16 + lr;
                #pragma unroll
                for (int nt = 0; nt < 4; ++nt) {
                    const int i0 = nt * 8 + lc * 2;
                    float2 v0; v0.x = cc[mt][nt][0]; v0.y = cc[mt][nt][1];
                    float2 v1; v1.x = cc[mt][nt][2]; v1.y = cc[mt][nt][3];
                    *reinterpret_cast<float2*>(ob + q * 32 + i0) = v0;
                    *reinterpret_cast<float2*>(ob + (q + 8) * 32 + i0) = v1;
                }
            }
        }
    }
}

extern "C" void kernel_launch(void* const* d_in, const int* in_sizes, int n_in,
                              void* d_out, int out_size) {
    const float* x  = (const float*)d_in[0];
    const float* w0 = (const float*)d_in[1];
    const float* w1 = (const float*)d_in[2];
    const float* w2 = (const float*)d_in[3];
    float* out = (float*)d_out;

    int batch = in_sizes[0] / ELEMS;   // 1024

    cudaFuncSetAttribute(kron3_mma_kernel,
                         cudaFuncAttributeMaxDynamicSharedMemorySize, SMEM_TOTAL);
    kron3_mma_kernel<<<batch, NT, SMEM_TOTAL>>>(x, w0, w1, w2, out);
}